// round 16
// baseline (speedup 1.0000x reference)
#include <cuda_runtime.h>
#include <cuda_fp16.h>
#include <math.h>

#define T_SEQ 4096
#define HID   1024
#define G4    4096
#define KDIM  1024
#define KP    2048   // fp16 2-term split: [Ahi|Alo] x [B|B]
#define REC_NC 128

typedef unsigned short u16;
typedef unsigned int   u32;

__device__ float g_pre[2][T_SEQ][G4];
__device__ u16 g_Abf[2][(size_t)T_SEQ * KP];   // A' = [Ahi|Alo] fp16
__device__ u16 g_Bbf[(size_t)G4 * KP];         // B' = [B|B] fp16
__device__ float g_hfin[2][HID];
__device__ __align__(8) float2 g_pubA[2][HID];
__device__ __align__(8) float2 g_pubB[2][HID];

__device__ __forceinline__ void split_f16(float x, u16& hi, u16& lo) {
    __half h = __float2half_rn(x);
    float r = x - __half2float(h);
    __half l = __float2half_rn(r);
    hi = *(u16*)&h; lo = *(u16*)&l;
}

// A' from raw input sequences (layer 0 only): [Ahi|Alo]
__global__ void conv_A(const float* __restrict__ A0, const float* __restrict__ A1)
{
    const int z = blockIdx.z;
    const float* A = z ? A1 : A0;
    int e = (blockIdx.x * blockDim.x + threadIdx.x) * 4;
    int m = e >> 10, k = e & 1023;
    float4 x = *(const float4*)&A[e];
    ushort4 hi, lo;
    split_f16(x.x, hi.x, lo.x); split_f16(x.y, hi.y, lo.y);
    split_f16(x.z, hi.z, lo.z); split_f16(x.w, hi.w, lo.w);
    u16* row = &g_Abf[z][(size_t)m * KP];
    *(ushort4*)&row[k]        = hi;
    *(ushort4*)&row[1024 + k] = lo;
}

// B' = [B|B], single fp16 rounding
__global__ void conv_B(const float* __restrict__ W)
{
    int e = (blockIdx.x * blockDim.x + threadIdx.x) * 4;
    int n = e >> 10, k = e & 1023;
    float4 x = *(const float4*)&W[e];
    __half h0 = __float2half_rn(x.x), h1 = __float2half_rn(x.y);
    __half h2 = __float2half_rn(x.z), h3 = __float2half_rn(x.w);
    ushort4 hv = make_ushort4(*(u16*)&h0, *(u16*)&h1, *(u16*)&h2, *(u16*)&h3);
    u16* row = &g_Bbf[(size_t)n * KP];
    *(ushort4*)&row[k]        = hv;
    *(ushort4*)&row[1024 + k] = hv;
}

// ---------------- HMMA GEMM (R15 version; + pub reset in block 0) ----------
#define KC   32
#define KPAD 40
#define BUFB (128 * KPAD * 2)

__device__ __forceinline__ u32 cvta_s(const void* p) {
    return (u32)__cvta_generic_to_shared(p);
}
#define LDSM_X4(r0, r1, r2, r3, addr) \
    asm volatile("ldmatrix.sync.aligned.m8n8.x4.shared.b16 {%0,%1,%2,%3}, [%4];" \
                 : "=r"(r0), "=r"(r1), "=r"(r2), "=r"(r3) : "r"(addr))
#define MMA_F16(acc, a0, a1, a2, a3, b0, b1) \
    asm volatile( \
        "mma.sync.aligned.m16n8k16.row.col.f32.f16.f16.f32 " \
        "{%0,%1,%2,%3}, {%4,%5,%6,%7}, {%8,%9}, {%0,%1,%2,%3};\n" \
        : "+f"((acc)[0]), "+f"((acc)[1]), "+f"((acc)[2]), "+f"((acc)[3]) \
        : "r"(a0), "r"(a1), "r"(a2), "r"(a3), "r"(b0), "r"(b1))

__global__ void __launch_bounds__(256, 2)
hgemm_bias(const float* __restrict__ bi, const float* __restrict__ bh)
{
    __shared__ u16 As[2][128][KPAD];
    __shared__ u16 Bs[2][128][KPAD];

    const int z  = blockIdx.z;
    const int m0 = blockIdx.y * 128;
    const int n0 = blockIdx.x * 128;
    const int tid  = threadIdx.x;
    const int warp = tid >> 5;
    const int lane = tid & 31;
    const int g = lane >> 2, t = lane & 3;

    // block 0 resets the LL publish buffers for the following lstm_rec
    if (blockIdx.x == 0 && blockIdx.y == 0 && blockIdx.z == 0) {
        float2 zz = make_float2(0.f, 0.f);
        #pragma unroll
        for (int j = 0; j < 8; ++j) {
            ((float2*)g_pubA)[tid + j * 256] = zz;
            ((float2*)g_pubB)[tid + j * 256] = zz;
        }
    }

    const int wm = (warp & 3) * 32;
    const int wn = (warp >> 2) * 64;

    const u16* Ag = &g_Abf[z][0];
    const u16* Bg = &g_Bbf[0];
    float* C = &g_pre[z][0][0];

    const int srow = tid >> 2;
    const int scol = (tid & 3) * 8;

    const u32 aAddr0 = cvta_s(&As[0][wm + (lane & 15)][(lane >> 4) * 8]);
    const u32 bAddr0 = cvta_s(&Bs[0][wn + (lane & 7) + ((lane >> 4) * 8)]
                                    [((lane >> 3) & 1) * 8]);

    float acc[2][8][4];
    #pragma unroll
    for (int i = 0; i < 2; ++i)
        #pragma unroll
        for (int j = 0; j < 8; ++j)
            #pragma unroll
            for (int q = 0; q < 4; ++q) acc[i][j][q] = 0.f;

    {
        *(float4*)&As[0][srow][scol] =
            *(const float4*)&Ag[(size_t)(m0 + srow) * KP + scol];
        *(float4*)&As[0][srow + 64][scol] =
            *(const float4*)&Ag[(size_t)(m0 + srow + 64) * KP + scol];
        *(float4*)&Bs[0][srow][scol] =
            *(const float4*)&Bg[(size_t)(n0 + srow) * KP + scol];
        *(float4*)&Bs[0][srow + 64][scol] =
            *(const float4*)&Bg[(size_t)(n0 + srow + 64) * KP + scol];
    }
    __syncthreads();

    int p = 0;
    const int NCHUNK = KP / KC;   // 64
    for (int c = 0; c < NCHUNK; ++c) {
        if (c + 1 < NCHUNK) {
            int kc = (c + 1) * KC;
            *(float4*)&As[p ^ 1][srow][scol] =
                *(const float4*)&Ag[(size_t)(m0 + srow) * KP + kc + scol];
            *(float4*)&As[p ^ 1][srow + 64][scol] =
                *(const float4*)&Ag[(size_t)(m0 + srow + 64) * KP + kc + scol];
            *(float4*)&Bs[p ^ 1][srow][scol] =
                *(const float4*)&Bg[(size_t)(n0 + srow) * KP + kc + scol];
            *(float4*)&Bs[p ^ 1][srow + 64][scol] =
                *(const float4*)&Bg[(size_t)(n0 + srow + 64) * KP + kc + scol];
        }
        const u32 aBase = aAddr0 + p * BUFB;
        const u32 bBase = bAddr0 + p * BUFB;
        #pragma unroll
        for (int ks = 0; ks < KC; ks += 16) {
            u32 af[2][4];
            #pragma unroll
            for (int i = 0; i < 2; ++i) {
                LDSM_X4(af[i][0], af[i][1], af[i][2], af[i][3],
                        aBase + i * (16 * KPAD * 2) + ks * 2);
            }
            #pragma unroll
            for (int j = 0; j < 8; j += 2) {
                u32 b0, b1, b2, b3;
                LDSM_X4(b0, b1, b2, b3, bBase + j * (8 * KPAD * 2) + ks * 2);
                #pragma unroll
                for (int i = 0; i < 2; ++i) {
                    MMA_F16(acc[i][j],     af[i][0], af[i][1], af[i][2], af[i][3], b0, b1);
                    MMA_F16(acc[i][j + 1], af[i][0], af[i][1], af[i][2], af[i][3], b2, b3);
                }
            }
        }
        p ^= 1;
        __syncthreads();
    }

    #pragma unroll
    for (int j = 0; j < 8; ++j) {
        int n = n0 + wn + 8 * j + 2 * t;
        float bs0 = __ldg(&bi[n])     + __ldg(&bh[n]);
        float bs1 = __ldg(&bi[n + 1]) + __ldg(&bh[n + 1]);
        #pragma unroll
        for (int i = 0; i < 2; ++i) {
            int m = m0 + wm + 16 * i + g;
            float2 v0 = make_float2(acc[i][j][0] + bs0, acc[i][j][1] + bs1);
            float2 v1 = make_float2(acc[i][j][2] + bs0, acc[i][j][3] + bs1);
            *(float2*)&C[(size_t)m * G4 + n]       = v0;
            *(float2*)&C[(size_t)(m + 8) * G4 + n] = v1;
        }
    }
}

// ---------------- recurrent kernel: BARRIER-FREE steps ----------------
// LL-tagged SMEM partials: producers st.volatile {partial, tag} and run ahead
// (throttled by tail_done >= t-1); tail warps spin on the 16 tags, release
// producers early (after reading, before nonlinear/publish).
#define SRED_PAD 33
#define SRED_BUF (16 * SRED_PAD)          // float2 slots per branch
#define REC_SMEM ((HID * 8) + (2 * SRED_BUF * 8) + 64)

__device__ __forceinline__ float sigm(float x) { return 1.f / (1.f + __expf(-x)); }

__device__ __forceinline__ void publish8(float2* p, float h, unsigned tag) {
    asm volatile("st.volatile.global.v2.f32 [%0], {%1,%2};"
                 :: "l"(p), "f"(h), "f"(__uint_as_float(tag)) : "memory");
}
__device__ __forceinline__ float2 poll8(const float2* p) {
    float2 v;
    asm volatile("ld.volatile.global.v2.f32 {%0,%1}, [%2];"
                 : "=f"(v.x), "=f"(v.y) : "l"(p) : "memory");
    return v;
}
__device__ __forceinline__ void sts8(u32 addr, float v, unsigned tag) {
    asm volatile("st.volatile.shared.v2.f32 [%0], {%1,%2};"
                 :: "r"(addr), "f"(v), "f"(__uint_as_float(tag)) : "memory");
}
__device__ __forceinline__ float2 lds8(u32 addr) {
    float2 v;
    asm volatile("ld.volatile.shared.v2.f32 {%0,%1}, [%2];"
                 : "=f"(v.x), "=f"(v.y) : "r"(addr) : "memory");
    return v;
}

__global__ void __launch_bounds__(512, 1)
lstm_rec(const float* __restrict__ Whh,
         const float* __restrict__ h0b0, const float* __restrict__ h0b1,
         const float* __restrict__ c0b0, const float* __restrict__ c0b1,
         int wr_abf)
{
    extern __shared__ float smemf[];
    float2* hs2  = (float2*)smemf;                       // 1024 float2
    float2* srA  = (float2*)(smemf + 2 * HID);           // [16][33] tagged
    float2* srB  = srA + SRED_BUF;                       // [16][33] tagged
    volatile int* tdone = (volatile int*)(srB + SRED_BUF);  // [2]

    const int tid  = threadIdx.x;
    const int warp = tid >> 5;
    const int lane = tid & 31;
    const int cta  = blockIdx.x;
    const int u0   = cta * 8;

    // zero sred tags + tail_done (per launch)
    for (int i = tid; i < 2 * SRED_BUF; i += 512)
        srA[i] = make_float2(0.f, 0.f);
    if (tid < 2) tdone[tid] = -1;

    const int gr_lane = (lane >> 3) * HID + u0 + (lane & 7);
    float4 wreg[16];
    {
        const float4* wrow = (const float4*)&Whh[(size_t)gr_lane * KDIM + warp * 64];
        #pragma unroll
        for (int j = 0; j < 16; ++j) wreg[j] = __ldg(&wrow[j]);
    }
    __syncthreads();   // one-time: SMEM init visible

    float cst = 0.f;
    if (warp == 0 && lane < 8) {
        cst = c0b0[u0 + lane];
        publish8(&g_pubA[0][u0 + lane], h0b0[u0 + lane], 1u);
    } else if (warp == 1 && lane < 8) {
        cst = c0b1[u0 + lane];
        publish8(&g_pubB[0][u0 + lane], h0b1[u0 + lane], 1u);
    }

    const float4* h4base = (const float4*)hs2 + warp * 32;
    const int uP0 = warp * 64 + lane;
    const int uP1 = warp * 64 + 32 + lane;
    const u32 myA = cvta_s(&srA[warp * SRED_PAD + lane]);
    const u32 myB = cvta_s(&srB[warp * SRED_PAD + lane]);

    for (int t = 0; t < T_SEQ; ++t) {
        const int p = t & 1;
        const unsigned tag = (unsigned)(t + 1);

        float pre = 0.f;
        if (warp == 0)      pre = __ldg(&g_pre[0][t][gr_lane]);
        else if (warp == 1) pre = __ldg(&g_pre[1][t][gr_lane]);

        // ---- poll own slice + wait for tails to have consumed step t-1 ----
        {
            const float2* pA = g_pubA[p];
            const float2* pB = g_pubB[p];
            float2 a0, a1, b0, b1;
            bool o0 = false, o1 = false, o2 = false, o3 = false, ot = false;
            do {
                if (!o0) { a0 = poll8(&pA[uP0]); o0 = (__float_as_uint(a0.y) == tag); }
                if (!o1) { a1 = poll8(&pA[uP1]); o1 = (__float_as_uint(a1.y) == tag); }
                if (!o2) { b0 = poll8(&pB[uP0]); o2 = (__float_as_uint(b0.y) == tag); }
                if (!o3) { b1 = poll8(&pB[uP1]); o3 = (__float_as_uint(b1.y) == tag); }
                if (!ot) { ot = (tdone[0] >= t - 1) && (tdone[1] >= t - 1); }
            } while (!(o0 & o1 & o2 & o3 & ot));
            hs2[uP0] = make_float2(a0.x, b0.x);
            hs2[uP1] = make_float2(a1.x, b1.x);
        }
        __syncwarp();   // own slice staged

        // ---- matvec ----
        float accA = 0.f, accB = 0.f;
        #pragma unroll
        for (int j = 0; j < 16; ++j) {
            float4 w   = wreg[j];
            float4 h0v = h4base[j * 2];
            float4 h1v = h4base[j * 2 + 1];
            accA = fmaf(w.x, h0v.x, accA); accB = fmaf(w.x, h0v.y, accB);
            accA = fmaf(w.y, h0v.z, accA); accB = fmaf(w.y, h0v.w, accB);
            accA = fmaf(w.z, h1v.x, accA); accB = fmaf(w.z, h1v.y, accB);
            accA = fmaf(w.w, h1v.z, accA); accB = fmaf(w.w, h1v.w, accB);
        }
        sts8(myA, accA, tag);
        sts8(myB, accB, tag);
        // producers (warps 2..15) immediately continue to next step's poll

        if (warp < 2) {
            const u32 srBase = (warp == 0) ? cvta_s(srA) : cvta_s(srB);
            float s = pre;
            #pragma unroll 1
            for (int w = 0; w < 16; ++w) {
                float2 v;
                do { v = lds8(srBase + (w * SRED_PAD + lane) * 8); }
                while (__float_as_uint(v.y) != tag);
                s += v.x;
            }
            __syncwarp();
            if (lane == 0) tdone[warp] = t;   // early release
            const int u = lane & 7;
            float gi = __shfl_sync(0xffffffffu, s, u);
            float gf = __shfl_sync(0xffffffffu, s, u + 8);
            float gg = __shfl_sync(0xffffffffu, s, u + 16);
            float go = __shfl_sync(0xffffffffu, s, u + 24);
            if (lane < 8) {
                cst = sigm(gf) * cst + sigm(gi) * tanhf(gg);
                float hv = sigm(go) * tanhf(cst);
                const int b = warp;
                if (b == 0) publish8(&g_pubA[p ^ 1][u0 + u], hv, (unsigned)(t + 2));
                else        publish8(&g_pubB[p ^ 1][u0 + u], hv, (unsigned)(t + 2));
                if (wr_abf) {
                    u16 hi, lo; split_f16(hv, hi, lo);
                    u16* row = &g_Abf[b][(size_t)t * KP];
                    row[u0 + u]        = hi;
                    row[1024 + u0 + u] = lo;
                }
                if (t == T_SEQ - 1) g_hfin[b][u0 + u] = hv;
            }
        }
    }
}

__global__ void final_k(float* __restrict__ out)
{
    __shared__ float red[256];
    int tid = threadIdx.x;
    float s = 0.f;
    for (int j = tid; j < HID; j += 256)
        s += fabsf(g_hfin[0][j] - g_hfin[1][j]);
    red[tid] = s;
    __syncthreads();
    for (int w = 128; w > 0; w >>= 1) {
        if (tid < w) red[tid] += red[tid + w];
        __syncthreads();
    }
    if (tid == 0) out[0] = 5.f * expf(-red[0]);
}

extern "C" void kernel_launch(void* const* d_in, const int* in_sizes, int n_in,
                              void* d_out, int out_size)
{
    const float* s1   = (const float*)d_in[0];
    const float* s2   = (const float*)d_in[1];
    const float* h1_0 = (const float*)d_in[2];
    const float* c1_0 = (const float*)d_in[3];
    const float* h2_0 = (const float*)d_in[4];
    const float* c2_0 = (const float*)d_in[5];
    const float* W_ih = (const float*)d_in[6];
    const float* W_hh = (const float*)d_in[7];
    const float* b_ih = (const float*)d_in[8];
    const float* b_hh = (const float*)d_in[9];

    cudaFuncSetAttribute(lstm_rec, cudaFuncAttributeMaxDynamicSharedMemorySize, REC_SMEM);

    dim3 gConvA(4096, 1, 2);
    dim3 gConvB(4096, 1, 1);
    dim3 gGemm(32, 32, 2);

    // layer 0 (hgemm block 0 resets pub buffers; rec tail writes A' for L1)
    conv_A<<<gConvA, 256>>>(s1, s2);
    conv_B<<<gConvB, 256>>>(W_ih);
    hgemm_bias<<<gGemm, 256>>>(b_ih, b_hh);
    lstm_rec<<<REC_NC, 512, REC_SMEM>>>(W_hh, h1_0, h2_0, c1_0, c2_0, 1);

    // layer 1
    const size_t woff = (size_t)G4 * KDIM;
    conv_B<<<gConvB, 256>>>(W_ih + woff);
    hgemm_bias<<<gGemm, 256>>>(b_ih + G4, b_hh + G4);
    lstm_rec<<<REC_NC, 512, REC_SMEM>>>(W_hh + woff, h1_0 + HID, h2_0 + HID,
                                        c1_0 + HID, c2_0 + HID, 0);

    final_k<<<1, 256>>>((float*)d_out);
}

// round 17
// speedup vs baseline: 2.2134x; 2.2134x over previous
#include <cuda_runtime.h>
#include <cuda_fp16.h>
#include <math.h>

#define T_SEQ 4096
#define HID   1024
#define G4    4096
#define KDIM  1024
#define KP    2048   // fp16 2-term split: [Ahi|Alo] x [B|B]
#define REC_NC 128

typedef unsigned short u16;
typedef unsigned int   u32;

__device__ float g_pre[2][T_SEQ][G4];
__device__ u16 g_Abf[2][(size_t)T_SEQ * KP];   // A' = [Ahi|Alo] fp16
__device__ u16 g_Bbf[(size_t)G4 * KP];         // B' = [B|B] fp16
__device__ float g_hfin[2][HID];
__device__ __align__(8) float2 g_pubA[2][HID];
__device__ __align__(8) float2 g_pubB[2][HID];

__device__ __forceinline__ void split_f16(float x, u16& hi, u16& lo) {
    __half h = __float2half_rn(x);
    float r = x - __half2float(h);
    __half l = __float2half_rn(r);
    hi = *(u16*)&h; lo = *(u16*)&l;
}

// A' from raw input sequences (layer 0 only): [Ahi|Alo]
__global__ void conv_A(const float* __restrict__ A0, const float* __restrict__ A1)
{
    const int z = blockIdx.z;
    const float* A = z ? A1 : A0;
    int e = (blockIdx.x * blockDim.x + threadIdx.x) * 4;
    int m = e >> 10, k = e & 1023;
    float4 x = *(const float4*)&A[e];
    ushort4 hi, lo;
    split_f16(x.x, hi.x, lo.x); split_f16(x.y, hi.y, lo.y);
    split_f16(x.z, hi.z, lo.z); split_f16(x.w, hi.w, lo.w);
    u16* row = &g_Abf[z][(size_t)m * KP];
    *(ushort4*)&row[k]        = hi;
    *(ushort4*)&row[1024 + k] = lo;
}

// B' = [B|B], single fp16 rounding
__global__ void conv_B(const float* __restrict__ W)
{
    int e = (blockIdx.x * blockDim.x + threadIdx.x) * 4;
    int n = e >> 10, k = e & 1023;
    float4 x = *(const float4*)&W[e];
    __half h0 = __float2half_rn(x.x), h1 = __float2half_rn(x.y);
    __half h2 = __float2half_rn(x.z), h3 = __float2half_rn(x.w);
    ushort4 hv = make_ushort4(*(u16*)&h0, *(u16*)&h1, *(u16*)&h2, *(u16*)&h3);
    u16* row = &g_Bbf[(size_t)n * KP];
    *(ushort4*)&row[k]        = hv;
    *(ushort4*)&row[1024 + k] = hv;
}

// ---------------- HMMA GEMM (R15; block 0 also resets pub buffers) ----------
#define KC   32
#define KPAD 40
#define BUFB (128 * KPAD * 2)

__device__ __forceinline__ u32 cvta_s(const void* p) {
    return (u32)__cvta_generic_to_shared(p);
}
#define LDSM_X4(r0, r1, r2, r3, addr) \
    asm volatile("ldmatrix.sync.aligned.m8n8.x4.shared.b16 {%0,%1,%2,%3}, [%4];" \
                 : "=r"(r0), "=r"(r1), "=r"(r2), "=r"(r3) : "r"(addr))
#define MMA_F16(acc, a0, a1, a2, a3, b0, b1) \
    asm volatile( \
        "mma.sync.aligned.m16n8k16.row.col.f32.f16.f16.f32 " \
        "{%0,%1,%2,%3}, {%4,%5,%6,%7}, {%8,%9}, {%0,%1,%2,%3};\n" \
        : "+f"((acc)[0]), "+f"((acc)[1]), "+f"((acc)[2]), "+f"((acc)[3]) \
        : "r"(a0), "r"(a1), "r"(a2), "r"(a3), "r"(b0), "r"(b1))

__global__ void __launch_bounds__(256, 2)
hgemm_bias(const float* __restrict__ bi, const float* __restrict__ bh)
{
    __shared__ u16 As[2][128][KPAD];
    __shared__ u16 Bs[2][128][KPAD];

    const int z  = blockIdx.z;
    const int m0 = blockIdx.y * 128;
    const int n0 = blockIdx.x * 128;
    const int tid  = threadIdx.x;
    const int warp = tid >> 5;
    const int lane = tid & 31;
    const int g = lane >> 2, t = lane & 3;

    // block 0 resets the LL publish buffers for the following lstm_rec
    if (blockIdx.x == 0 && blockIdx.y == 0 && blockIdx.z == 0) {
        float2 zz = make_float2(0.f, 0.f);
        #pragma unroll
        for (int j = 0; j < 8; ++j) {
            ((float2*)g_pubA)[tid + j * 256] = zz;
            ((float2*)g_pubB)[tid + j * 256] = zz;
        }
    }

    const int wm = (warp & 3) * 32;
    const int wn = (warp >> 2) * 64;

    const u16* Ag = &g_Abf[z][0];
    const u16* Bg = &g_Bbf[0];
    float* C = &g_pre[z][0][0];

    const int srow = tid >> 2;
    const int scol = (tid & 3) * 8;

    const u32 aAddr0 = cvta_s(&As[0][wm + (lane & 15)][(lane >> 4) * 8]);
    const u32 bAddr0 = cvta_s(&Bs[0][wn + (lane & 7) + ((lane >> 4) * 8)]
                                    [((lane >> 3) & 1) * 8]);

    float acc[2][8][4];
    #pragma unroll
    for (int i = 0; i < 2; ++i)
        #pragma unroll
        for (int j = 0; j < 8; ++j)
            #pragma unroll
            for (int q = 0; q < 4; ++q) acc[i][j][q] = 0.f;

    {
        *(float4*)&As[0][srow][scol] =
            *(const float4*)&Ag[(size_t)(m0 + srow) * KP + scol];
        *(float4*)&As[0][srow + 64][scol] =
            *(const float4*)&Ag[(size_t)(m0 + srow + 64) * KP + scol];
        *(float4*)&Bs[0][srow][scol] =
            *(const float4*)&Bg[(size_t)(n0 + srow) * KP + scol];
        *(float4*)&Bs[0][srow + 64][scol] =
            *(const float4*)&Bg[(size_t)(n0 + srow + 64) * KP + scol];
    }
    __syncthreads();

    int p = 0;
    const int NCHUNK = KP / KC;   // 64
    for (int c = 0; c < NCHUNK; ++c) {
        if (c + 1 < NCHUNK) {
            int kc = (c + 1) * KC;
            *(float4*)&As[p ^ 1][srow][scol] =
                *(const float4*)&Ag[(size_t)(m0 + srow) * KP + kc + scol];
            *(float4*)&As[p ^ 1][srow + 64][scol] =
                *(const float4*)&Ag[(size_t)(m0 + srow + 64) * KP + kc + scol];
            *(float4*)&Bs[p ^ 1][srow][scol] =
                *(const float4*)&Bg[(size_t)(n0 + srow) * KP + kc + scol];
            *(float4*)&Bs[p ^ 1][srow + 64][scol] =
                *(const float4*)&Bg[(size_t)(n0 + srow + 64) * KP + kc + scol];
        }
        const u32 aBase = aAddr0 + p * BUFB;
        const u32 bBase = bAddr0 + p * BUFB;
        #pragma unroll
        for (int ks = 0; ks < KC; ks += 16) {
            u32 af[2][4];
            #pragma unroll
            for (int i = 0; i < 2; ++i) {
                LDSM_X4(af[i][0], af[i][1], af[i][2], af[i][3],
                        aBase + i * (16 * KPAD * 2) + ks * 2);
            }
            #pragma unroll
            for (int j = 0; j < 8; j += 2) {
                u32 b0, b1, b2, b3;
                LDSM_X4(b0, b1, b2, b3, bBase + j * (8 * KPAD * 2) + ks * 2);
                #pragma unroll
                for (int i = 0; i < 2; ++i) {
                    MMA_F16(acc[i][j],     af[i][0], af[i][1], af[i][2], af[i][3], b0, b1);
                    MMA_F16(acc[i][j + 1], af[i][0], af[i][1], af[i][2], af[i][3], b2, b3);
                }
            }
        }
        p ^= 1;
        __syncthreads();
    }

    #pragma unroll
    for (int j = 0; j < 8; ++j) {
        int n = n0 + wn + 8 * j + 2 * t;
        float bs0 = __ldg(&bi[n])     + __ldg(&bh[n]);
        float bs1 = __ldg(&bi[n + 1]) + __ldg(&bh[n + 1]);
        #pragma unroll
        for (int i = 0; i < 2; ++i) {
            int m = m0 + wm + 16 * i + g;
            float2 v0 = make_float2(acc[i][j][0] + bs0, acc[i][j][1] + bs1);
            float2 v1 = make_float2(acc[i][j][2] + bs0, acc[i][j][3] + bs1);
            *(float2*)&C[(size_t)m * G4 + n]       = v0;
            *(float2*)&C[(size_t)(m + 8) * G4 + n] = v1;
        }
    }
}

// ---------------- recurrent kernel (R15 structure, verbatim) ----------------
#define SRED_PAD 33
#define SRED_BUF (16 * SRED_PAD)
#define REC_SMEM ((HID * 8) + (4 * SRED_BUF * 4))

__device__ __forceinline__ float sigm(float x) { return 1.f / (1.f + __expf(-x)); }

__device__ __forceinline__ void publish8(float2* p, float h, unsigned tag) {
    asm volatile("st.volatile.global.v2.f32 [%0], {%1,%2};"
                 :: "l"(p), "f"(h), "f"(__uint_as_float(tag)) : "memory");
}
__device__ __forceinline__ float2 poll8(const float2* p) {
    float2 v;
    asm volatile("ld.volatile.global.v2.f32 {%0,%1}, [%2];"
                 : "=f"(v.x), "=f"(v.y) : "l"(p) : "memory");
    return v;
}

__global__ void __launch_bounds__(512, 1)
lstm_rec(const float* __restrict__ Whh,
         const float* __restrict__ h0b0, const float* __restrict__ h0b1,
         const float* __restrict__ c0b0, const float* __restrict__ c0b1,
         int wr_abf)
{
    extern __shared__ float smemf[];
    float2* hs2   = (float2*)smemf;
    float*  sredA = smemf + 2 * HID;
    float*  sredB = smemf + 2 * HID + 2 * SRED_BUF;

    const int tid  = threadIdx.x;
    const int warp = tid >> 5;
    const int lane = tid & 31;
    const int cta  = blockIdx.x;
    const int u0   = cta * 8;

    const int gr_lane = (lane >> 3) * HID + u0 + (lane & 7);
    float4 wreg[16];
    {
        const float4* wrow = (const float4*)&Whh[(size_t)gr_lane * KDIM + warp * 64];
        #pragma unroll
        for (int j = 0; j < 16; ++j) wreg[j] = __ldg(&wrow[j]);
    }

    float cst = 0.f;
    if (warp == 0 && lane < 8) {
        cst = c0b0[u0 + lane];
        publish8(&g_pubA[0][u0 + lane], h0b0[u0 + lane], 1u);
    } else if (warp == 1 && lane < 8) {
        cst = c0b1[u0 + lane];
        publish8(&g_pubB[0][u0 + lane], h0b1[u0 + lane], 1u);
    }

    const float4* h4base = (const float4*)hs2 + warp * 32;
    const int uP0 = warp * 64 + lane;
    const int uP1 = warp * 64 + 32 + lane;

    for (int t = 0; t < T_SEQ; ++t) {
        const int p = t & 1;
        const unsigned tag = (unsigned)(t + 1);

        float pre = 0.f;
        if (warp == 0)      pre = __ldg(&g_pre[0][t][gr_lane]);
        else if (warp == 1) pre = __ldg(&g_pre[1][t][gr_lane]);

        {
            const float2* pA = g_pubA[p];
            const float2* pB = g_pubB[p];
            float2 a0, a1, b0, b1;
            bool o0 = false, o1 = false, o2 = false, o3 = false;
            do {
                if (!o0) { a0 = poll8(&pA[uP0]); o0 = (__float_as_uint(a0.y) == tag); }
                if (!o1) { a1 = poll8(&pA[uP1]); o1 = (__float_as_uint(a1.y) == tag); }
                if (!o2) { b0 = poll8(&pB[uP0]); o2 = (__float_as_uint(b0.y) == tag); }
                if (!o3) { b1 = poll8(&pB[uP1]); o3 = (__float_as_uint(b1.y) == tag); }
            } while (!(o0 & o1 & o2 & o3));
            hs2[uP0] = make_float2(a0.x, b0.x);
            hs2[uP1] = make_float2(a1.x, b1.x);
        }
        __syncwarp();

        float accA = 0.f, accB = 0.f;
        #pragma unroll
        for (int j = 0; j < 16; ++j) {
            float4 w   = wreg[j];
            float4 h0v = h4base[j * 2];
            float4 h1v = h4base[j * 2 + 1];
            accA = fmaf(w.x, h0v.x, accA); accB = fmaf(w.x, h0v.y, accB);
            accA = fmaf(w.y, h0v.z, accA); accB = fmaf(w.y, h0v.w, accB);
            accA = fmaf(w.z, h1v.x, accA); accB = fmaf(w.z, h1v.y, accB);
            accA = fmaf(w.w, h1v.z, accA); accB = fmaf(w.w, h1v.w, accB);
        }
        sredA[p * SRED_BUF + warp * SRED_PAD + lane] = accA;
        sredB[p * SRED_BUF + warp * SRED_PAD + lane] = accB;
        __syncthreads();

        if (warp < 2) {
            const float* sr = (warp == 0) ? &sredA[p * SRED_BUF] : &sredB[p * SRED_BUF];
            float s = pre;
            #pragma unroll
            for (int w = 0; w < 16; ++w) s += sr[w * SRED_PAD + lane];
            const int u = lane & 7;
            float gi = __shfl_sync(0xffffffffu, s, u);
            float gf = __shfl_sync(0xffffffffu, s, u + 8);
            float gg = __shfl_sync(0xffffffffu, s, u + 16);
            float go = __shfl_sync(0xffffffffu, s, u + 24);
            if (lane < 8) {
                cst = sigm(gf) * cst + sigm(gi) * tanhf(gg);
                float hv = sigm(go) * tanhf(cst);
                const int b = warp;
                if (b == 0) publish8(&g_pubA[p ^ 1][u0 + u], hv, (unsigned)(t + 2));
                else        publish8(&g_pubB[p ^ 1][u0 + u], hv, (unsigned)(t + 2));
                if (wr_abf) {
                    u16 hi, lo; split_f16(hv, hi, lo);
                    u16* row = &g_Abf[b][(size_t)t * KP];
                    row[u0 + u]        = hi;
                    row[1024 + u0 + u] = lo;
                }
                if (t == T_SEQ - 1) g_hfin[b][u0 + u] = hv;
            }
        }
    }
}

__global__ void final_k(float* __restrict__ out)
{
    __shared__ float red[256];
    int tid = threadIdx.x;
    float s = 0.f;
    for (int j = tid; j < HID; j += 256)
        s += fabsf(g_hfin[0][j] - g_hfin[1][j]);
    red[tid] = s;
    __syncthreads();
    for (int w = 128; w > 0; w >>= 1) {
        if (tid < w) red[tid] += red[tid + w];
        __syncthreads();
    }
    if (tid == 0) out[0] = 5.f * expf(-red[0]);
}

extern "C" void kernel_launch(void* const* d_in, const int* in_sizes, int n_in,
                              void* d_out, int out_size)
{
    const float* s1   = (const float*)d_in[0];
    const float* s2   = (const float*)d_in[1];
    const float* h1_0 = (const float*)d_in[2];
    const float* c1_0 = (const float*)d_in[3];
    const float* h2_0 = (const float*)d_in[4];
    const float* c2_0 = (const float*)d_in[5];
    const float* W_ih = (const float*)d_in[6];
    const float* W_hh = (const float*)d_in[7];
    const float* b_ih = (const float*)d_in[8];
    const float* b_hh = (const float*)d_in[9];

    cudaFuncSetAttribute(lstm_rec, cudaFuncAttributeMaxDynamicSharedMemorySize, REC_SMEM);

    dim3 gConvA(4096, 1, 2);
    dim3 gConvB(4096, 1, 1);
    dim3 gGemm(32, 32, 2);

    // layer 0 (hgemm block 0 resets pub buffers; rec tail writes A' for L1)
    conv_A<<<gConvA, 256>>>(s1, s2);
    conv_B<<<gConvB, 256>>>(W_ih);
    hgemm_bias<<<gGemm, 256>>>(b_ih, b_hh);
    lstm_rec<<<REC_NC, 512, REC_SMEM>>>(W_hh, h1_0, h2_0, c1_0, c2_0, 1);

    // layer 1
    const size_t woff = (size_t)G4 * KDIM;
    conv_B<<<gConvB, 256>>>(W_ih + woff);
    hgemm_bias<<<gGemm, 256>>>(b_ih + G4, b_hh + G4);
    lstm_rec<<<REC_NC, 512, REC_SMEM>>>(W_hh + woff, h1_0 + HID, h2_0 + HID,
                                        c1_0 + HID, c2_0 + HID, 0);

    final_k<<<1, 256>>>((float*)d_out);
}